// round 6
// baseline (speedup 1.0000x reference)
#include <cuda_runtime.h>

#define TS    100
#define BB    256
#define DOBS  64
#define DFEAT 512
#define DLAT  512
#define DOUTD 64

// d_out layout (element offsets): outs, hs, thetas, ys, delta_outs
#define OUTS_OFF 0
#define HS_OFF   (TS*BB*DOUTD)
#define TH_OFF   (HS_OFF + TS*BB*DLAT)
#define YS_OFF   (TH_OFF + TS*BB*DLAT)
#define DO_OFF   (YS_OFF + TS*BB*DLAT)

typedef unsigned long long ull;

// packed f32x2 helpers (each lane is an independent IEEE fp32 RN op)
__device__ __forceinline__ ull fma2(ull a, ull b, ull c) {
    ull d; asm("fma.rn.f32x2 %0, %1, %2, %3;" : "=l"(d) : "l"(a), "l"(b), "l"(c)); return d;
}
__device__ __forceinline__ ull add2(ull a, ull b) {
    ull d; asm("add.rn.f32x2 %0, %1, %2;" : "=l"(d) : "l"(a), "l"(b)); return d;
}
__device__ __forceinline__ float2 unpack2(ull v) {
    float2 f; asm("mov.b64 {%0, %1}, %2;" : "=f"(f.x), "=f"(f.y) : "l"(v)); return f;
}

// persistent state across kernels of the scan
__device__ float g_x[BB * DFEAT];    // x(t) = tanh(x_in @ W_pre + b_pre)
__device__ float g_xin[BB * DOBS];   // x_in(t)

// ---------------------------------------------------------------------------
// Fused dual-GEMM phase kernel (v3: 256 threads = 8 warps for latency hiding).
// A = [x | h_src] (B x 1024). acc1 = A@W1, acc2 = A@W2 for a 32x32 tile.
// A duplicated in smem so one LDS.128 yields two f32x2 broadcast pairs.
// Per-element FMA order (k sequence + per-32k stage partial folds) is
// bit-identical to the R4/R5 kernels; only the thread mapping changed.
// PHASE 0: g/theta/h (writes hs[t], thetas[t]); PHASE 1: y (writes ys[t]).
// grid = (16, 8); 256 threads; each thread: 2 rows x 2 cols x 2 matrices.
// ---------------------------------------------------------------------------
template <int PHASE>
__global__ __launch_bounds__(256) void phase_kernel(
    const float* __restrict__ W1, const float* __restrict__ b1,
    const float* __restrict__ W2, const float* __restrict__ b2,
    const float* __restrict__ noise_t,  // [B][DLAT] slice (phase 0 only)
    const float* __restrict__ h_src,    // [B][512]; nullptr => zeros (t==0)
    float* __restrict__ out1,           // hs[t] or ys[t] slice
    float* __restrict__ out_th)         // thetas[t] slice (phase 0)
{
    __shared__ float As[2][32][72];   // duplicated: [k][2*row+{0,1}]
    __shared__ float B1s[2][32][32];  // [k][col]
    __shared__ float B2s[2][32][32];

    const int tid = threadIdx.x;
    const int m0 = blockIdx.y * 32;
    const int n0 = blockIdx.x * 32;
    const int rp = tid >> 4;        // 0..15 -> rows 2*rp, 2*rp+1
    const int r0 = rp * 2;
    const int c0 = (tid & 15) * 2;  // 0..30 (even -> 8B-aligned b64 pair)

    const int nstage = (h_src == nullptr) ? 16 : 32;  // K=512 at t==0 phase A

    ull acc1[2] = {0ull, 0ull};   // (0.f, 0.f) bit pattern
    ull acc2[2] = {0ull, 0ull};

    auto loadA = [&](int stage, int buf) {
        const int k0 = stage * 32;
        const float* src;
        int kbase;
        if (k0 < 512) { src = g_x;   kbase = k0; }
        else          { src = h_src; kbase = k0 - 512; }
        // 256 float4 slots, one per thread
        int row = tid >> 3, q = tid & 7;
        float4 v = *(const float4*)&src[(size_t)(m0 + row) * 512 + kbase + q * 4];
        *(float2*)&As[buf][q * 4 + 0][2 * row] = make_float2(v.x, v.x);
        *(float2*)&As[buf][q * 4 + 1][2 * row] = make_float2(v.y, v.y);
        *(float2*)&As[buf][q * 4 + 2][2 * row] = make_float2(v.z, v.z);
        *(float2*)&As[buf][q * 4 + 3][2 * row] = make_float2(v.w, v.w);
    };
    auto loadB = [&](int stage, int buf) {
        const int k0 = stage * 32;
        int k = tid >> 3, q = tid & 7;
        *(float4*)&B1s[buf][k][q * 4] =
            *(const float4*)&W1[(size_t)(k0 + k) * 512 + n0 + q * 4];
        *(float4*)&B2s[buf][k][q * 4] =
            *(const float4*)&W2[(size_t)(k0 + k) * 512 + n0 + q * 4];
    };

    loadA(0, 0);
    loadB(0, 0);
    __syncthreads();

    for (int s = 0; s < nstage; s++) {
        const int buf = s & 1;
        if (s + 1 < nstage) { loadA(s + 1, buf ^ 1); loadB(s + 1, buf ^ 1); }

        // stage-local partial accumulators (shorter rounding chains)
        ull p1[2] = {0ull, 0ull};
        ull p2[2] = {0ull, 0ull};
#pragma unroll
        for (int kk = 0; kk < 32; kk++) {
            // one LDS.128: (a[r0],a[r0]),(a[r0+1],a[r0+1])
            ulonglong2 a01 = *(const ulonglong2*)&As[buf][kk][2 * r0];
            ull w1p = *(const ull*)&B1s[buf][kk][c0];   // (w1[c0], w1[c0+1])
            ull w2p = *(const ull*)&B2s[buf][kk][c0];
            p1[0] = fma2(a01.x, w1p, p1[0]);
            p2[0] = fma2(a01.x, w2p, p2[0]);
            p1[1] = fma2(a01.y, w1p, p1[1]);
            p2[1] = fma2(a01.y, w2p, p2[1]);
        }
        acc1[0] = add2(acc1[0], p1[0]);
        acc1[1] = add2(acc1[1], p1[1]);
        acc2[0] = add2(acc2[0], p2[0]);
        acc2[1] = add2(acc2[1], p2[1]);
        __syncthreads();
    }

#pragma unroll
    for (int i = 0; i < 2; i++) {
        const int b = m0 + r0 + i;
        float2 v1 = unpack2(acc1[i]);
        float2 v2 = unpack2(acc2[i]);
        float a1v[2] = {v1.x, v1.y};
        float a2v[2] = {v2.x, v2.y};
#pragma unroll
        for (int c = 0; c < 2; c++) {
            const int n = n0 + c0 + c;
            if (PHASE == 0) {
                double z = (double)a1v[c] + (double)b1[n]
                         + (double)noise_t[b * DLAT + n];
                float th = (z > 0.0) ? 1.f : 0.f;
                double g  = (z > 0.0) ? tanh(z) : 0.0;
                double hp = h_src ? (double)h_src[b * DLAT + n] : 0.0;
                double rl = (double)a2v[c] + (double)b2[n];
                float h = (float)(g * tanh(rl) + (1.0 - g) * hp);
                out1[b * DLAT + n]   = h;
                out_th[b * DLAT + n] = th;
            } else {
                double p = (double)a1v[c] + (double)b1[n];
                double o = (double)a2v[c] + (double)b2[n];
                float y = (float)(tanh(p) / (1.0 + exp(-o)));
                out1[b * DLAT + n] = y;
            }
        }
    }
}

// ---------------------------------------------------------------------------
// Output + next-step-prep kernel, v3: 128 blocks x 256 threads, 2 rows/block.
// Explicit register preload batches force deep MLP into SASS so the L2-hit
// weight loads overlap instead of serializing. Per-element accumulation
// order is unchanged from v2 (64-chunk partials for W_out, 16-chunk for W_pre).
// ---------------------------------------------------------------------------
__global__ __launch_bounds__(256) void out_kernel(
    const float* __restrict__ y_t,
    const float* __restrict__ W_out, const float* __restrict__ b_out,
    const float* __restrict__ obs_n,   // obs[t+1] slice, or nullptr
    const float* __restrict__ mask_n,  // sampling_mask[t+1] slice
    const float* __restrict__ W_pre, const float* __restrict__ b_pre,
    float* __restrict__ outs_t, float* __restrict__ douts_t,
    int force_m)
{
    __shared__ float ysm[2][512];
    __shared__ float red[2][64];    // half-1 K-partials
    __shared__ float outm[2][64];
    __shared__ float xinm[2][64];

    const int tid = threadIdx.x;
    const int b0 = blockIdx.x * 2;

    if (y_t) {
        // load 2 rows of y (256 float4 slots)
        {
            int r = tid >> 7, q = tid & 127;
            *(float4*)&ysm[r][q * 4] =
                *(const float4*)&y_t[(size_t)(b0 + r) * 512 + q * 4];
        }
        __syncthreads();

        // thread: o = col, r = row, half = K-half (256 each, 4 chunks of 64)
        const int o = tid & 63;
        const int rh = tid >> 6;      // 0..3
        const int r = rh & 1;
        const int half = rh >> 1;
        float acc = 0.f;
        const int fbase = half * 256;
        for (int fc = 0; fc < 256; fc += 64) {
            // preload the 64-chunk of W_out column in two 32-deep batches
            float wreg[32];
            float pa = 0.f;
#pragma unroll
            for (int j = 0; j < 32; j++)
                wreg[j] = W_out[(fbase + fc + j) * 64 + o];
#pragma unroll
            for (int j = 0; j < 32; j++)
                pa += ysm[r][fbase + fc + j] * wreg[j];
#pragma unroll
            for (int j = 0; j < 32; j++)
                wreg[j] = W_out[(fbase + fc + 32 + j) * 64 + o];
#pragma unroll
            for (int j = 0; j < 32; j++)
                pa += ysm[r][fbase + fc + 32 + j] * wreg[j];
            acc += pa;
        }
        if (half == 1) red[r][o] = acc;
        __syncthreads();
        if (half == 0) {
            float tot = acc + red[r][o] + b_out[o];
            const int b = b0 + r;
            float outv = g_xin[b * 64 + o] + tot;
            outs_t[b * 64 + o]  = outv;
            douts_t[b * 64 + o] = tot;
            outm[r][o] = outv;
        }
        __syncthreads();
    }

    if (obs_n) {
        // x_in for the 2 rows (first 128 threads)
        if (tid < 128) {
            const int r = tid >> 6;
            const int o = tid & 63;
            const int b = b0 + r;
            float m = force_m ? 1.f : ((mask_n[b] < 0.5f) ? 1.f : 0.f);
            float xin = (m != 0.f) ? obs_n[b * 64 + o] : outm[r][o];
            g_xin[b * 64 + o] = xin;
            xinm[r][o] = xin;
        }
        __syncthreads();

        // x = tanh(x_in @ W_pre + b_pre): 2 rows x 512 feats; thread = 4 feats
        const int r2 = tid >> 7;            // 0..1
        const int f0 = (tid & 127) * 4;     // 4 contiguous feats
        float accM[4] = {0.f, 0.f, 0.f, 0.f};
        for (int oc = 0; oc < 64; oc += 16) {
            // preload 16 float4 (64 regs) -> 16 outstanding LDGs
            float4 wreg[16];
#pragma unroll
            for (int o2i = 0; o2i < 16; o2i++)
                wreg[o2i] = *(const float4*)&W_pre[(oc + o2i) * 512 + f0];
            float accP[4] = {0.f, 0.f, 0.f, 0.f};
#pragma unroll
            for (int o2i = 0; o2i < 16; o2i++) {
                float xv = xinm[r2][oc + o2i];
                accP[0] += xv * wreg[o2i].x;
                accP[1] += xv * wreg[o2i].y;
                accP[2] += xv * wreg[o2i].z;
                accP[3] += xv * wreg[o2i].w;
            }
#pragma unroll
            for (int j = 0; j < 4; j++) accM[j] += accP[j];
        }
#pragma unroll
        for (int j = 0; j < 4; j++)
            g_x[(size_t)(b0 + r2) * 512 + f0 + j] =
                (float)tanh((double)accM[j] + (double)b_pre[f0 + j]);
    }
}

// ---------------------------------------------------------------------------
extern "C" void kernel_launch(void* const* d_in, const int* in_sizes, int n_in,
                              void* d_out, int out_size)
{
    (void)in_sizes; (void)n_in; (void)out_size;
    const float* obs   = (const float*)d_in[0];
    const float* smask = (const float*)d_in[1];
    const float* noise = (const float*)d_in[2];
    const float* W_pre = (const float*)d_in[3];
    const float* b_pre = (const float*)d_in[4];
    const float* Wg    = (const float*)d_in[5];
    const float* bg    = (const float*)d_in[6];
    const float* Wr    = (const float*)d_in[7];
    const float* br    = (const float*)d_in[8];
    const float* Wp    = (const float*)d_in[9];
    const float* bp    = (const float*)d_in[10];
    const float* Wo    = (const float*)d_in[11];
    const float* bo    = (const float*)d_in[12];
    const float* W_out = (const float*)d_in[13];
    const float* b_out = (const float*)d_in[14];

    float* out  = (float*)d_out;
    float* outs = out + OUTS_OFF;
    float* hs   = out + HS_OFF;
    float* ths  = out + TH_OFF;
    float* ys   = out + YS_OFF;
    float* dos_ = out + DO_OFF;

    dim3 pgrid(16, 8);

    // t = 0 prep: x_in(0) = obs[0] (mask forced to 1), x(0) = tanh(x_in @ W_pre + b)
    out_kernel<<<128, 256>>>(nullptr, W_out, b_out,
                             obs, smask, W_pre, b_pre,
                             nullptr, nullptr, /*force_m=*/1);

    for (int t = 0; t < TS; t++) {
        const float* hprev = (t == 0) ? nullptr : hs + (size_t)(t - 1) * BB * DLAT;
        float* ht  = hs  + (size_t)t * BB * DLAT;
        float* tht = ths + (size_t)t * BB * DLAT;
        float* yt  = ys  + (size_t)t * BB * DLAT;

        phase_kernel<0><<<pgrid, 256>>>(Wg, bg, Wr, br,
                                        noise + (size_t)t * BB * DLAT,
                                        hprev, ht, tht);
        phase_kernel<1><<<pgrid, 256>>>(Wp, bp, Wo, bo,
                                        nullptr, ht, yt, nullptr);

        const float* obs_n  = (t + 1 < TS) ? obs + (size_t)(t + 1) * BB * DOBS : nullptr;
        const float* mask_n = (t + 1 < TS) ? smask + (size_t)(t + 1) * BB : nullptr;
        out_kernel<<<128, 256>>>(yt, W_out, b_out,
                                 obs_n, mask_n, W_pre, b_pre,
                                 outs + (size_t)t * BB * DOUTD,
                                 dos_ + (size_t)t * BB * DOUTD,
                                 /*force_m=*/0);
    }
}

// round 7
// speedup vs baseline: 1.0985x; 1.0985x over previous
#include <cuda_runtime.h>

#define TS    100
#define BB    256
#define DOBS  64
#define DFEAT 512
#define DLAT  512
#define DOUTD 64

// d_out layout (element offsets): outs, hs, thetas, ys, delta_outs
#define OUTS_OFF 0
#define HS_OFF   (TS*BB*DOUTD)
#define TH_OFF   (HS_OFF + TS*BB*DLAT)
#define YS_OFF   (TH_OFF + TS*BB*DLAT)
#define DO_OFF   (YS_OFF + TS*BB*DLAT)

typedef unsigned long long ull;

// packed f32x2 helpers (each lane is an independent IEEE fp32 RN op)
__device__ __forceinline__ ull fma2(ull a, ull b, ull c) {
    ull d; asm("fma.rn.f32x2 %0, %1, %2, %3;" : "=l"(d) : "l"(a), "l"(b), "l"(c)); return d;
}
__device__ __forceinline__ ull add2(ull a, ull b) {
    ull d; asm("add.rn.f32x2 %0, %1, %2;" : "=l"(d) : "l"(a), "l"(b)); return d;
}
__device__ __forceinline__ float2 unpack2(ull v) {
    float2 f; asm("mov.b64 {%0, %1}, %2;" : "=f"(f.x), "=f"(f.y) : "l"(v)); return f;
}

// persistent state across kernels of the scan
__device__ float g_x[BB * DFEAT];    // x(t) = tanh(x_in @ W_pre + b_pre)
__device__ float g_xin[BB * DOBS];   // x_in(t)

// ---------------------------------------------------------------------------
// Fused dual-GEMM phase kernel (v4).
// Mainloop: explicit reg-prefetch double-buffer pipeline; FMA order and the
// per-32k stage-partial folds are BIT-IDENTICAL to the R4/R5/R6 kernels.
// Epilogue: z / rl composed with double adds (theta sign test identical to
// R4), transcendentals in precise fp32 (tanhf/expf; harness is not fast-math).
// PHASE 0: g/theta/h (writes hs[t], thetas[t]); PHASE 1: y (writes ys[t]).
// grid = (16, 8); 256 threads; each thread: 2 rows x 2 cols x 2 matrices.
// ---------------------------------------------------------------------------
template <int PHASE>
__global__ __launch_bounds__(256) void phase_kernel(
    const float* __restrict__ W1, const float* __restrict__ b1,
    const float* __restrict__ W2, const float* __restrict__ b2,
    const float* __restrict__ noise_t,  // [B][DLAT] slice (phase 0 only)
    const float* __restrict__ h_src,    // [B][512]; nullptr => zeros (t==0)
    float* __restrict__ out1,           // hs[t] or ys[t] slice
    float* __restrict__ out_th)         // thetas[t] slice (phase 0)
{
    __shared__ float As[2][32][72];   // duplicated: [k][2*row+{0,1}]
    __shared__ float B1s[2][32][32];  // [k][col]
    __shared__ float B2s[2][32][32];

    const int tid = threadIdx.x;
    const int m0 = blockIdx.y * 32;
    const int n0 = blockIdx.x * 32;
    const int r0 = (tid >> 4) * 2;   // rows r0, r0+1
    const int c0 = (tid & 15) * 2;   // cols c0, c0+1 (8B-aligned b64 pair)

    const int nstage = (h_src == nullptr) ? 16 : 32;  // K=512 at t==0 phase A

    // per-thread load coordinates (one float4 per tile per stage)
    const int arow = tid >> 3, aq = tid & 7;   // A: row 0..31, quad 0..7
    const int bk   = tid >> 3, bq = tid & 7;   // B: k 0..31, quad 0..7

    ull acc1[2] = {0ull, 0ull};
    ull acc2[2] = {0ull, 0ull};

    auto ldA = [&](int stage) -> float4 {
        const int k0 = stage * 32;
        const float* src;
        int kbase;
        if (k0 < 512) { src = g_x;   kbase = k0; }
        else          { src = h_src; kbase = k0 - 512; }
        return *(const float4*)&src[(size_t)(m0 + arow) * 512 + kbase + aq * 4];
    };
    auto ldB = [&](const float* W, int stage) -> float4 {
        const int k0 = stage * 32;
        return *(const float4*)&W[(size_t)(k0 + bk) * 512 + n0 + bq * 4];
    };
    auto stA = [&](float4 v, int buf) {
        *(float2*)&As[buf][aq * 4 + 0][2 * arow] = make_float2(v.x, v.x);
        *(float2*)&As[buf][aq * 4 + 1][2 * arow] = make_float2(v.y, v.y);
        *(float2*)&As[buf][aq * 4 + 2][2 * arow] = make_float2(v.z, v.z);
        *(float2*)&As[buf][aq * 4 + 3][2 * arow] = make_float2(v.w, v.w);
    };

    {
        float4 a0 = ldA(0), w1v = ldB(W1, 0), w2v = ldB(W2, 0);
        stA(a0, 0);
        *(float4*)&B1s[0][bk][bq * 4] = w1v;
        *(float4*)&B2s[0][bk][bq * 4] = w2v;
    }
    __syncthreads();

    for (int s = 0; s < nstage; s++) {
        const int buf = s & 1;
        float4 aNxt, w1Nxt, w2Nxt;
        const bool more = (s + 1 < nstage);
        if (more) {
            aNxt  = ldA(s + 1);
            w1Nxt = ldB(W1, s + 1);
            w2Nxt = ldB(W2, s + 1);
        }

        // stage-local partial accumulators (shorter rounding chains)
        ull p1[2] = {0ull, 0ull};
        ull p2[2] = {0ull, 0ull};
#pragma unroll
        for (int kk = 0; kk < 32; kk++) {
            ulonglong2 a01 = *(const ulonglong2*)&As[buf][kk][2 * r0];
            ull w1p = *(const ull*)&B1s[buf][kk][c0];
            ull w2p = *(const ull*)&B2s[buf][kk][c0];
            p1[0] = fma2(a01.x, w1p, p1[0]);
            p2[0] = fma2(a01.x, w2p, p2[0]);
            p1[1] = fma2(a01.y, w1p, p1[1]);
            p2[1] = fma2(a01.y, w2p, p2[1]);
        }
        acc1[0] = add2(acc1[0], p1[0]);
        acc1[1] = add2(acc1[1], p1[1]);
        acc2[0] = add2(acc2[0], p2[0]);
        acc2[1] = add2(acc2[1], p2[1]);

        if (more) {
            stA(aNxt, buf ^ 1);
            *(float4*)&B1s[buf ^ 1][bk][bq * 4] = w1Nxt;
            *(float4*)&B2s[buf ^ 1][bk][bq * 4] = w2Nxt;
        }
        __syncthreads();
    }

#pragma unroll
    for (int i = 0; i < 2; i++) {
        const int b = m0 + r0 + i;
        float2 v1 = unpack2(acc1[i]);
        float2 v2 = unpack2(acc2[i]);
        float a1v[2] = {v1.x, v1.y};
        float a2v[2] = {v2.x, v2.y};
#pragma unroll
        for (int c = 0; c < 2; c++) {
            const int n = n0 + c0 + c;
            if (PHASE == 0) {
                // z composed in double: theta sign decision identical to R4
                double z = (double)a1v[c] + (double)b1[n]
                         + (double)noise_t[b * DLAT + n];
                float th = (z > 0.0) ? 1.f : 0.f;
                float g  = (z > 0.0) ? tanhf((float)z) : 0.f;
                float hp = h_src ? h_src[b * DLAT + n] : 0.f;
                float rl = (float)((double)a2v[c] + (double)b2[n]);
                float h  = g * tanhf(rl) + (1.f - g) * hp;
                out1[b * DLAT + n]   = h;
                out_th[b * DLAT + n] = th;
            } else {
                float p = (float)((double)a1v[c] + (double)b1[n]);
                float o = (float)((double)a2v[c] + (double)b2[n]);
                float y = tanhf(p) / (1.f + expf(-o));
                out1[b * DLAT + n] = y;
            }
        }
    }
}

// ---------------------------------------------------------------------------
// Output + next-step-prep kernel, v4: 128 blocks x 256 threads, 2 rows/block.
// fp32 tanhf epilogue (arg composed with a double add); forced unrolls.
// ---------------------------------------------------------------------------
__global__ __launch_bounds__(256) void out_kernel(
    const float* __restrict__ y_t,
    const float* __restrict__ W_out, const float* __restrict__ b_out,
    const float* __restrict__ obs_n,   // obs[t+1] slice, or nullptr
    const float* __restrict__ mask_n,  // sampling_mask[t+1] slice
    const float* __restrict__ W_pre, const float* __restrict__ b_pre,
    float* __restrict__ outs_t, float* __restrict__ douts_t,
    int force_m)
{
    __shared__ float ysm[2][512];
    __shared__ float red[2][64];    // half-1 K-partials
    __shared__ float outm[2][64];
    __shared__ float xinm[2][64];

    const int tid = threadIdx.x;
    const int b0 = blockIdx.x * 2;

    if (y_t) {
        {
            int r = tid >> 7, q = tid & 127;
            *(float4*)&ysm[r][q * 4] =
                *(const float4*)&y_t[(size_t)(b0 + r) * 512 + q * 4];
        }
        __syncthreads();

        const int o = tid & 63;
        const int rh = tid >> 6;      // 0..3
        const int r = rh & 1;
        const int half = rh >> 1;
        float acc = 0.f;
        const int fbase = half * 256;
#pragma unroll
        for (int fc = 0; fc < 256; fc += 64) {
            float wreg[32];
            float pa = 0.f;
#pragma unroll
            for (int j = 0; j < 32; j++)
                wreg[j] = W_out[(fbase + fc + j) * 64 + o];
#pragma unroll
            for (int j = 0; j < 32; j++)
                pa += ysm[r][fbase + fc + j] * wreg[j];
#pragma unroll
            for (int j = 0; j < 32; j++)
                wreg[j] = W_out[(fbase + fc + 32 + j) * 64 + o];
#pragma unroll
            for (int j = 0; j < 32; j++)
                pa += ysm[r][fbase + fc + 32 + j] * wreg[j];
            acc += pa;
        }
        if (half == 1) red[r][o] = acc;
        __syncthreads();
        if (half == 0) {
            float tot = acc + red[r][o] + b_out[o];
            const int b = b0 + r;
            float outv = g_xin[b * 64 + o] + tot;
            outs_t[b * 64 + o]  = outv;
            douts_t[b * 64 + o] = tot;
            outm[r][o] = outv;
        }
        __syncthreads();
    }

    if (obs_n) {
        if (tid < 128) {
            const int r = tid >> 6;
            const int o = tid & 63;
            const int b = b0 + r;
            float m = force_m ? 1.f : ((mask_n[b] < 0.5f) ? 1.f : 0.f);
            float xin = (m != 0.f) ? obs_n[b * 64 + o] : outm[r][o];
            g_xin[b * 64 + o] = xin;
            xinm[r][o] = xin;
        }
        __syncthreads();

        // x = tanh(x_in @ W_pre + b_pre): 2 rows x 512 feats; thread = 4 feats
        const int r2 = tid >> 7;            // 0..1
        const int f0 = (tid & 127) * 4;     // 4 contiguous feats
        float accM[4] = {0.f, 0.f, 0.f, 0.f};
#pragma unroll
        for (int oc = 0; oc < 64; oc += 16) {
            float4 wreg[16];
#pragma unroll
            for (int o2i = 0; o2i < 16; o2i++)
                wreg[o2i] = *(const float4*)&W_pre[(oc + o2i) * 512 + f0];
            float accP[4] = {0.f, 0.f, 0.f, 0.f};
#pragma unroll
            for (int o2i = 0; o2i < 16; o2i++) {
                float xv = xinm[r2][oc + o2i];
                accP[0] += xv * wreg[o2i].x;
                accP[1] += xv * wreg[o2i].y;
                accP[2] += xv * wreg[o2i].z;
                accP[3] += xv * wreg[o2i].w;
            }
#pragma unroll
            for (int j = 0; j < 4; j++) accM[j] += accP[j];
        }
#pragma unroll
        for (int j = 0; j < 4; j++)
            g_x[(size_t)(b0 + r2) * 512 + f0 + j] =
                tanhf((float)((double)accM[j] + (double)b_pre[f0 + j]));
    }
}

// ---------------------------------------------------------------------------
extern "C" void kernel_launch(void* const* d_in, const int* in_sizes, int n_in,
                              void* d_out, int out_size)
{
    (void)in_sizes; (void)n_in; (void)out_size;
    const float* obs   = (const float*)d_in[0];
    const float* smask = (const float*)d_in[1];
    const float* noise = (const float*)d_in[2];
    const float* W_pre = (const float*)d_in[3];
    const float* b_pre = (const float*)d_in[4];
    const float* Wg    = (const float*)d_in[5];
    const float* bg    = (const float*)d_in[6];
    const float* Wr    = (const float*)d_in[7];
    const float* br    = (const float*)d_in[8];
    const float* Wp    = (const float*)d_in[9];
    const float* bp    = (const float*)d_in[10];
    const float* Wo    = (const float*)d_in[11];
    const float* bo    = (const float*)d_in[12];
    const float* W_out = (const float*)d_in[13];
    const float* b_out = (const float*)d_in[14];

    float* out  = (float*)d_out;
    float* outs = out + OUTS_OFF;
    float* hs   = out + HS_OFF;
    float* ths  = out + TH_OFF;
    float* ys   = out + YS_OFF;
    float* dos_ = out + DO_OFF;

    dim3 pgrid(16, 8);

    // t = 0 prep: x_in(0) = obs[0] (mask forced to 1), x(0) = tanh(x_in @ W_pre + b)
    out_kernel<<<128, 256>>>(nullptr, W_out, b_out,
                             obs, smask, W_pre, b_pre,
                             nullptr, nullptr, /*force_m=*/1);

    for (int t = 0; t < TS; t++) {
        const float* hprev = (t == 0) ? nullptr : hs + (size_t)(t - 1) * BB * DLAT;
        float* ht  = hs  + (size_t)t * BB * DLAT;
        float* tht = ths + (size_t)t * BB * DLAT;
        float* yt  = ys  + (size_t)t * BB * DLAT;

        phase_kernel<0><<<pgrid, 256>>>(Wg, bg, Wr, br,
                                        noise + (size_t)t * BB * DLAT,
                                        hprev, ht, tht);
        phase_kernel<1><<<pgrid, 256>>>(Wp, bp, Wo, bo,
                                        nullptr, ht, yt, nullptr);

        const float* obs_n  = (t + 1 < TS) ? obs + (size_t)(t + 1) * BB * DOBS : nullptr;
        const float* mask_n = (t + 1 < TS) ? smask + (size_t)(t + 1) * BB : nullptr;
        out_kernel<<<128, 256>>>(yt, W_out, b_out,
                                 obs_n, mask_n, W_pre, b_pre,
                                 outs + (size_t)t * BB * DOUTD,
                                 dos_ + (size_t)t * BB * DOUTD,
                                 /*force_m=*/0);
    }
}

// round 9
// speedup vs baseline: 1.1002x; 1.0015x over previous
#include <cuda_runtime.h>

#define TS    100
#define BB    256
#define DOBS  64
#define DFEAT 512
#define DLAT  512
#define DOUTD 64

// d_out layout (element offsets): outs, hs, thetas, ys, delta_outs
#define OUTS_OFF 0
#define HS_OFF   (TS*BB*DOUTD)
#define TH_OFF   (HS_OFF + TS*BB*DLAT)
#define YS_OFF   (TH_OFF + TS*BB*DLAT)
#define DO_OFF   (YS_OFF + TS*BB*DLAT)

typedef unsigned long long ull;

// packed f32x2 helpers (each lane is an independent IEEE fp32 RN op)
__device__ __forceinline__ ull fma2(ull a, ull b, ull c) {
    ull d; asm("fma.rn.f32x2 %0, %1, %2, %3;" : "=l"(d) : "l"(a), "l"(b), "l"(c)); return d;
}
__device__ __forceinline__ ull add2(ull a, ull b) {
    ull d; asm("add.rn.f32x2 %0, %1, %2;" : "=l"(d) : "l"(a), "l"(b)); return d;
}
__device__ __forceinline__ float2 unpack2(ull v) {
    float2 f; asm("mov.b64 {%0, %1}, %2;" : "=f"(f.x), "=f"(f.y) : "l"(v)); return f;
}

// forced (volatile => not sinkable/reorderable by ptxas) global loads
#define LDG4(dst, p) \
    asm volatile("ld.global.v4.f32 {%0,%1,%2,%3}, [%4];" \
                 : "=f"((dst).x), "=f"((dst).y), "=f"((dst).z), "=f"((dst).w) \
                 : "l"(p))
#define LDG4NC(dst, p) \
    asm volatile("ld.global.nc.v4.f32 {%0,%1,%2,%3}, [%4];" \
                 : "=f"((dst).x), "=f"((dst).y), "=f"((dst).z), "=f"((dst).w) \
                 : "l"(p))
#define LDGF(dst, p) \
    asm volatile("ld.global.nc.f32 %0, [%1];" : "=f"(dst) : "l"(p))

// persistent state across kernels of the scan
__device__ float g_x[BB * DFEAT];    // x(t) = tanh(x_in @ W_pre + b_pre)
__device__ float g_xin[BB * DOBS];   // x_in(t)

// ---------------------------------------------------------------------------
// Fused dual-GEMM phase kernel (v5).
// Mainloop FMA order + per-32k stage-partial folds BIT-IDENTICAL to R4.
// PF=2 software pipeline: LDG for stage s+2 issued at top of stage s (held in
// registers one full extra stage before its STS) -> LDG latency fully hidden.
// Epilogue: R4-exact fp64 (tanh/exp in double, one final round to fp32).
// grid = (16, 8); 256 threads; thread: 2 rows x 2 cols x 2 matrices.
// ---------------------------------------------------------------------------
template <int PHASE>
__global__ __launch_bounds__(256) void phase_kernel(
    const float* __restrict__ W1, const float* __restrict__ b1,
    const float* __restrict__ W2, const float* __restrict__ b2,
    const float* __restrict__ noise_t,  // [B][DLAT] slice (phase 0 only)
    const float* __restrict__ h_src,    // [B][512]; nullptr => zeros (t==0)
    float* __restrict__ out1,           // hs[t] or ys[t] slice
    float* __restrict__ out_th)         // thetas[t] slice (phase 0)
{
    __shared__ float As[2][32][72];   // duplicated: [k][2*row+{0,1}]
    __shared__ float B1s[2][32][32];  // [k][col]
    __shared__ float B2s[2][32][32];

    const int tid = threadIdx.x;
    const int m0 = blockIdx.y * 32;
    const int n0 = blockIdx.x * 32;
    const int r0 = (tid >> 4) * 2;   // rows r0, r0+1
    const int c0 = (tid & 15) * 2;   // cols c0, c0+1 (8B-aligned b64 pair)

    const int nstage = (h_src == nullptr) ? 16 : 32;  // K=512 at t==0 phase A

    const int arow = tid >> 3, aq = tid & 7;   // A: row 0..31, quad 0..7
    const int bk   = tid >> 3, bq = tid & 7;   // B: k 0..31, quad 0..7

    ull acc1[2] = {0ull, 0ull};
    ull acc2[2] = {0ull, 0ull};

    auto aPtr = [&](int stage) -> const float* {
        const int k0 = stage * 32;
        const float* src;
        int kbase;
        if (k0 < 512) { src = g_x;   kbase = k0; }
        else          { src = h_src; kbase = k0 - 512; }
        return &src[(size_t)(m0 + arow) * 512 + kbase + aq * 4];
    };
    auto bPtr = [&](const float* W, int stage) -> const float* {
        return &W[(size_t)(stage * 32 + bk) * 512 + n0 + bq * 4];
    };
    auto stA = [&](float4 v, int buf) {
        *(float2*)&As[buf][aq * 4 + 0][2 * arow] = make_float2(v.x, v.x);
        *(float2*)&As[buf][aq * 4 + 1][2 * arow] = make_float2(v.y, v.y);
        *(float2*)&As[buf][aq * 4 + 2][2 * arow] = make_float2(v.z, v.z);
        *(float2*)&As[buf][aq * 4 + 3][2 * arow] = make_float2(v.w, v.w);
    };
    auto stB = [&](float4 w1v, float4 w2v, int buf) {
        *(float4*)&B1s[buf][bk][bq * 4] = w1v;
        *(float4*)&B2s[buf][bk][bq * 4] = w2v;
    };
    auto compute = [&](int buf) {
        ull p1[2] = {0ull, 0ull};
        ull p2[2] = {0ull, 0ull};
#pragma unroll
        for (int kk = 0; kk < 32; kk++) {
            ulonglong2 a01 = *(const ulonglong2*)&As[buf][kk][2 * r0];
            ull w1p = *(const ull*)&B1s[buf][kk][c0];
            ull w2p = *(const ull*)&B2s[buf][kk][c0];
            p1[0] = fma2(a01.x, w1p, p1[0]);
            p2[0] = fma2(a01.x, w2p, p2[0]);
            p1[1] = fma2(a01.y, w1p, p1[1]);
            p2[1] = fma2(a01.y, w2p, p2[1]);
        }
        acc1[0] = add2(acc1[0], p1[0]);
        acc1[1] = add2(acc1[1], p1[1]);
        acc2[0] = add2(acc2[0], p2[0]);
        acc2[1] = add2(acc2[1], p2[1]);
    };

    // ---- pipeline prologue: stage 0 -> smem, stage 1 -> registers ----
    {
        float4 a0, w10, w20;
        LDG4(a0, aPtr(0));
        LDG4NC(w10, bPtr(W1, 0));
        LDG4NC(w20, bPtr(W2, 0));
        stA(a0, 0);
        stB(w10, w20, 0);
    }
    float4 aR, w1R, w2R;     // data for the NEXT odd/even stage (s+1)
    LDG4(aR, aPtr(1));
    LDG4NC(w1R, bPtr(W1, 1));
    LDG4NC(w2R, bPtr(W2, 1));
    __syncthreads();

    // ---- mainloop, 2 stages per iteration (even buf 0, odd buf 1) ----
    for (int s = 0; s < nstage; s += 2) {
        // stage s (buf 0): issue LDG(s+2), compute, STS regs(s+1) -> buf 1
        float4 aN2, w1N2, w2N2;
        const bool have2 = (s + 2 < nstage);
        if (have2) {
            LDG4(aN2, aPtr(s + 2));
            LDG4NC(w1N2, bPtr(W1, s + 2));
            LDG4NC(w2N2, bPtr(W2, s + 2));
        }
        compute(0);
        stA(aR, 1);
        stB(w1R, w2R, 1);
        __syncthreads();

        // stage s+1 (buf 1): issue LDG(s+3), compute, STS regs(s+2) -> buf 0
        float4 aN3, w1N3, w2N3;
        const bool have3 = (s + 3 < nstage);
        if (have3) {
            LDG4(aN3, aPtr(s + 3));
            LDG4NC(w1N3, bPtr(W1, s + 3));
            LDG4NC(w2N3, bPtr(W2, s + 3));
        }
        compute(1);
        if (have2) {
            stA(aN2, 0);
            stB(w1N2, w2N2, 0);
        }
        __syncthreads();

        if (have3) { aR = aN3; w1R = w1N3; w2R = w2N3; }
    }

    // ---- epilogue: R4-exact fp64 ----
#pragma unroll
    for (int i = 0; i < 2; i++) {
        const int b = m0 + r0 + i;
        float2 v1 = unpack2(acc1[i]);
        float2 v2 = unpack2(acc2[i]);
        float a1v[2] = {v1.x, v1.y};
        float a2v[2] = {v2.x, v2.y};
#pragma unroll
        for (int c = 0; c < 2; c++) {
            const int n = n0 + c0 + c;
            if (PHASE == 0) {
                double z = (double)a1v[c] + (double)b1[n]
                         + (double)noise_t[b * DLAT + n];
                float th = (z > 0.0) ? 1.f : 0.f;
                double g  = (z > 0.0) ? tanh(z) : 0.0;
                double hp = h_src ? (double)h_src[b * DLAT + n] : 0.0;
                double rl = (double)a2v[c] + (double)b2[n];
                float h = (float)(g * tanh(rl) + (1.0 - g) * hp);
                out1[b * DLAT + n]   = h;
                out_th[b * DLAT + n] = th;
            } else {
                double p = (double)a1v[c] + (double)b1[n];
                double o = (double)a2v[c] + (double)b2[n];
                float y = (float)(tanh(p) / (1.0 + exp(-o)));
                out1[b * DLAT + n] = y;
            }
        }
    }
}

// ---------------------------------------------------------------------------
// Output + next-step-prep kernel, v5: 128 blocks x 256 threads, 2 rows/block.
// All weight loads via asm-volatile batches (MLP forced into SASS).
// Accumulation chunk order identical to R5-R7; x-prep tanh in fp64 (R4-exact).
// ---------------------------------------------------------------------------
__global__ __launch_bounds__(256) void out_kernel(
    const float* __restrict__ y_t,
    const float* __restrict__ W_out, const float* __restrict__ b_out,
    const float* __restrict__ obs_n,   // obs[t+1] slice, or nullptr
    const float* __restrict__ mask_n,  // sampling_mask[t+1] slice
    const float* __restrict__ W_pre, const float* __restrict__ b_pre,
    float* __restrict__ outs_t, float* __restrict__ douts_t,
    int force_m)
{
    __shared__ float ysm[2][512];
    __shared__ float red[2][64];    // half-1 K-partials
    __shared__ float outm[2][64];
    __shared__ float xinm[2][64];

    const int tid = threadIdx.x;
    const int b0 = blockIdx.x * 2;

    if (y_t) {
        {
            int r = tid >> 7, q = tid & 127;
            float4 v;
            LDG4(v, &y_t[(size_t)(b0 + r) * 512 + q * 4]);
            *(float4*)&ysm[r][q * 4] = v;
        }
        __syncthreads();

        const int o = tid & 63;
        const int rh = tid >> 6;      // 0..3
        const int r = rh & 1;
        const int half = rh >> 1;
        float acc = 0.f;
        const int fbase = half * 256;
#pragma unroll
        for (int fc = 0; fc < 256; fc += 64) {
            const float* wp = &W_out[(fbase + fc) * 64 + o];
            float wreg[32];
            float pa = 0.f;
#pragma unroll
            for (int j = 0; j < 32; j++) LDGF(wreg[j], wp + j * 64);
#pragma unroll
            for (int j = 0; j < 32; j++)
                pa += ysm[r][fbase + fc + j] * wreg[j];
#pragma unroll
            for (int j = 0; j < 32; j++) LDGF(wreg[j], wp + (32 + j) * 64);
#pragma unroll
            for (int j = 0; j < 32; j++)
                pa += ysm[r][fbase + fc + 32 + j] * wreg[j];
            acc += pa;
        }
        if (half == 1) red[r][o] = acc;
        __syncthreads();
        if (half == 0) {
            float tot = acc + red[r][o] + b_out[o];
            const int b = b0 + r;
            float outv = g_xin[b * 64 + o] + tot;
            outs_t[b * 64 + o]  = outv;
            douts_t[b * 64 + o] = tot;
            outm[r][o] = outv;
        }
        __syncthreads();
    }

    if (obs_n) {
        if (tid < 128) {
            const int r = tid >> 6;
            const int o = tid & 63;
            const int b = b0 + r;
            float m = force_m ? 1.f : ((mask_n[b] < 0.5f) ? 1.f : 0.f);
            float xin = (m != 0.f) ? obs_n[b * 64 + o] : outm[r][o];
            g_xin[b * 64 + o] = xin;
            xinm[r][o] = xin;
        }
        __syncthreads();

        // x = tanh(x_in @ W_pre + b_pre): 2 rows x 512 feats; thread = 4 feats
        const int r2 = tid >> 7;            // 0..1
        const int f0 = (tid & 127) * 4;     // 4 contiguous feats
        float accM[4] = {0.f, 0.f, 0.f, 0.f};
#pragma unroll
        for (int oc = 0; oc < 64; oc += 16) {
            float4 wreg[16];
#pragma unroll
            for (int o2i = 0; o2i < 16; o2i++)
                LDG4NC(wreg[o2i], &W_pre[(oc + o2i) * 512 + f0]);
            float accP[4] = {0.f, 0.f, 0.f, 0.f};
#pragma unroll
            for (int o2i = 0; o2i < 16; o2i++) {
                float xv = xinm[r2][oc + o2i];
                accP[0] += xv * wreg[o2i].x;
                accP[1] += xv * wreg[o2i].y;
                accP[2] += xv * wreg[o2i].z;
                accP[3] += xv * wreg[o2i].w;
            }
#pragma unroll
            for (int j = 0; j < 4; j++) accM[j] += accP[j];
        }
#pragma unroll
        for (int j = 0; j < 4; j++)
            g_x[(size_t)(b0 + r2) * 512 + f0 + j] =
                (float)tanh((double)accM[j] + (double)b_pre[f0 + j]);
    }
}

// ---------------------------------------------------------------------------
extern "C" void kernel_launch(void* const* d_in, const int* in_sizes, int n_in,
                              void* d_out, int out_size)
{
    (void)in_sizes; (void)n_in; (void)out_size;
    const float* obs   = (const float*)d_in[0];
    const float* smask = (const float*)d_in[1];
    const float* noise = (const float*)d_in[2];
    const float* W_pre = (const float*)d_in[3];
    const float* b_pre = (const float*)d_in[4];
    const float* Wg    = (const float*)d_in[5];
    const float* bg    = (const float*)d_in[6];
    const float* Wr    = (const float*)d_in[7];
    const float* br    = (const float*)d_in[8];
    const float* Wp    = (const float*)d_in[9];
    const float* bp    = (const float*)d_in[10];
    const float* Wo    = (const float*)d_in[11];
    const float* bo    = (const float*)d_in[12];
    const float* W_out = (const float*)d_in[13];
    const float* b_out = (const float*)d_in[14];

    float* out  = (float*)d_out;
    float* outs = out + OUTS_OFF;
    float* hs   = out + HS_OFF;
    float* ths  = out + TH_OFF;
    float* ys   = out + YS_OFF;
    float* dos_ = out + DO_OFF;

    dim3 pgrid(16, 8);

    // t = 0 prep: x_in(0) = obs[0] (mask forced to 1), x(0) = tanh(x_in @ W_pre + b)
    out_kernel<<<128, 256>>>(nullptr, W_out, b_out,
                             obs, smask, W_pre, b_pre,
                             nullptr, nullptr, /*force_m=*/1);

    for (int t = 0; t < TS; t++) {
        const float* hprev = (t == 0) ? nullptr : hs + (size_t)(t - 1) * BB * DLAT;
        float* ht  = hs  + (size_t)t * BB * DLAT;
        float* tht = ths + (size_t)t * BB * DLAT;
        float* yt  = ys  + (size_t)t * BB * DLAT;

        phase_kernel<0><<<pgrid, 256>>>(Wg, bg, Wr, br,
                                        noise + (size_t)t * BB * DLAT,
                                        hprev, ht, tht);
        phase_kernel<1><<<pgrid, 256>>>(Wp, bp, Wo, bo,
                                        nullptr, ht, yt, nullptr);

        const float* obs_n  = (t + 1 < TS) ? obs + (size_t)(t + 1) * BB * DOBS : nullptr;
        const float* mask_n = (t + 1 < TS) ? smask + (size_t)(t + 1) * BB : nullptr;
        out_kernel<<<128, 256>>>(yt, W_out, b_out,
                                 obs_n, mask_n, W_pre, b_pre,
                                 outs + (size_t)t * BB * DOUTD,
                                 dos_ + (size_t)t * BB * DOUTD,
                                 /*force_m=*/0);
    }
}